// round 16
// baseline (speedup 1.0000x reference)
#include <cuda_runtime.h>
#include <math.h>
#include <stdint.h>

#define B_SZ 2
#define L 1024
#define D 384
#define PATCH_DIM 4096
#define DEPTH 12
#define DSTATE 16
#define DTRANK 24
#define DBL_N 56
#define NTOK (B_SZ * L)   // 2048
#define NCH 8             // scan chunks
#define CHL (L / NCH)     // 128 steps per chunk
#define SCH 8             // chains per scan block

typedef unsigned long long ull;

// ------------------------- scratch (static device) -------------------------
__device__ float g_tok[NTOK * D];
__device__ float g_h[NTOK * D];
__device__ float g_xz[NTOK * 2 * D];
__device__ float g_dbl[NTOK * DBL_N];
__device__ float g_y[NTOK * D];
__device__ float g_H[96 * NCH * 128];   // inclusive chunk states
__device__ int   g_flag[NCH * 96];      // publish flags (zeroed per layer by ln_k)

// ------------------------- cp.async + f32x2 helpers ------------------------
__device__ __forceinline__ void cp_async16(uint32_t dst, const void* src, bool pred) {
    int sz = pred ? 16 : 0;
    asm volatile("cp.async.ca.shared.global [%0], [%1], 16, %2;\n"
                 :: "r"(dst), "l"(src), "r"(sz));
}
__device__ __forceinline__ void cp_commit() {
    asm volatile("cp.async.commit_group;\n");
}
template <int N>
__device__ __forceinline__ void cp_wait() {
    asm volatile("cp.async.wait_group %0;\n" :: "n"(N));
}
__device__ __forceinline__ ull pack2(float x, float y) {
    ull r; asm("mov.b64 %0, {%1, %2};" : "=l"(r) : "f"(x), "f"(y)); return r;
}
__device__ __forceinline__ void unpack2(ull v, float& x, float& y) {
    asm("mov.b64 {%0, %1}, %2;" : "=f"(x), "=f"(y) : "l"(v));
}
__device__ __forceinline__ void ffma2(ull& d, ull a, ull b) {
    asm("fma.rn.f32x2 %0, %1, %2, %0;" : "+l"(d) : "l"(a), "l"(b));
}

// ------------------------- pipelined SGEMM 64x64 (vector LDS + FFMA2) ------
#define BM 64
#define BN 64
#define BK 16
#define ASTRIDE 20

struct SmemGemm {
    __align__(16) float As[2][BM * ASTRIDE];
    __align__(16) float Bs[2][BK * BN];
};

__device__ __forceinline__ void gemm_inner(const float* __restrict__ As,
                                           const float* __restrict__ Bsr,
                                           int m0, int n0, ull acc2[4][2])
{
    #pragma unroll
    for (int k4 = 0; k4 < BK; k4 += 4) {
        float4 a[4];
        #pragma unroll
        for (int i = 0; i < 4; i++)
            a[i] = *reinterpret_cast<const float4*>(&As[(m0 + i) * ASTRIDE + k4]);
        #pragma unroll
        for (int q = 0; q < 4; q++) {
            float4 bq = *reinterpret_cast<const float4*>(&Bsr[(k4 + q) * BN + n0]);
            ull b01 = pack2(bq.x, bq.y);
            ull b23 = pack2(bq.z, bq.w);
            #pragma unroll
            for (int i = 0; i < 4; i++) {
                const float* af = &a[i].x;
                ull ap = pack2(af[q], af[q]);
                ffma2(acc2[i][0], ap, b01);
                ffma2(acc2[i][1], ap, b23);
            }
        }
    }
}

// epi: 0 none, 1 +bias, 3 C += result.
// gridDim.z>1 -> split-K, partials accumulated via atomicAdd (bias ignored).
__global__ void sgemm_k(const float* __restrict__ A, int lda,
                        const float* __restrict__ Bm,
                        float* __restrict__ C,
                        const float* __restrict__ bias,
                        int M, int N, int K, int epi)
{
    __shared__ SmemGemm sm;
    const int bm = blockIdx.y * BM, bn = blockIdx.x * BN;
    const int tid = threadIdx.x;

    const int ksplit = gridDim.z;
    const int kc = K / ksplit;
    const int kstart = blockIdx.z * kc;
    const int kend = kstart + kc;
    const int niters = (kc + BK - 1) / BK;

    const int am  = tid >> 2;
    const int akq = (tid & 3) << 2;
    const int bkb = tid >> 4;
    const int bn4 = (tid & 15) << 2;
    const bool bn_ok = (bn + bn4) < N;

    const float* Arow = A + (size_t)(bm + am) * lda;

    uint32_t sAs = (uint32_t)__cvta_generic_to_shared(&sm.As[0][0]);
    uint32_t sBs = (uint32_t)__cvta_generic_to_shared(&sm.Bs[0][0]);

    auto load_stage = [&](int it, int buf) {
        int k0 = kstart + it * BK;
        {
            int k = k0 + akq;
            bool p = k < kend;
            const float* src = p ? (Arow + k) : A;
            cp_async16(sAs + (buf * BM * ASTRIDE + am * ASTRIDE + akq) * 4, src, p);
        }
        {
            int k = k0 + bkb;
            bool p = (k < kend) && bn_ok;
            const float* src = p ? (Bm + (size_t)k * N + bn + bn4) : Bm;
            cp_async16(sBs + (buf * BK * BN + bkb * BN + bn4) * 4, src, p);
        }
    };

    const int ty = tid >> 4, tx = tid & 15;
    const int m0 = ty * 4, n0 = tx * 4;

    ull acc2[4][2];
    #pragma unroll
    for (int i = 0; i < 4; i++) { acc2[i][0] = 0ull; acc2[i][1] = 0ull; }

    load_stage(0, 0); cp_commit();
    if (niters > 1) load_stage(1, 1);
    cp_commit();

    for (int it = 0; it < niters; it++) {
        cp_wait<1>();
        __syncthreads();
        const int buf = it & 1;
        gemm_inner(&sm.As[buf][0], &sm.Bs[buf][0], m0, n0, acc2);
        __syncthreads();
        if (it + 2 < niters) load_stage(it + 2, buf);
        cp_commit();
    }

    #pragma unroll
    for (int i = 0; i < 4; i++) {
        int row = bm + m0 + i;
        float v[4];
        unpack2(acc2[i][0], v[0], v[1]);
        unpack2(acc2[i][1], v[2], v[3]);
        #pragma unroll
        for (int j = 0; j < 4; j++) {
            int col = bn + n0 + j;
            if (col < N) {
                size_t off = (size_t)row * N + col;
                float vv = v[j];
                if (ksplit > 1) {
                    atomicAdd(&C[off], vv);
                } else {
                    if (epi == 1) vv += bias[col];
                    if (epi == 3) vv += C[off];
                    C[off] = vv;
                }
            }
        }
    }
}

// ------------------------- x_proj GEMM with inline conv+silu ----------------
// A[m][k] = silu(cb[k] + sum_j xz[(b, l-3+j)][k] * cw[k][j]) computed in regs.
// C = dbl (pre-zeroed), always atomicAdd (split-K). N = DBL_N, K = D.
__global__ void sgemm_xproj_k(const float* __restrict__ xz,
                              const float* __restrict__ cw,
                              const float* __restrict__ cb,
                              const float* __restrict__ Bm,
                              float* __restrict__ C)
{
    __shared__ SmemGemm sm;
    const int bm = blockIdx.y * BM;
    const int tid = threadIdx.x;
    const int N = DBL_N, K = D;

    const int ksplit = gridDim.z;
    const int kc = K / ksplit;
    const int kstart = blockIdx.z * kc;
    const int niters = kc / BK;

    const int am  = tid >> 2;
    const int akq = (tid & 3) << 2;
    const int bkb = tid >> 4;
    const int bn4 = (tid & 15) << 2;
    const bool bn_ok = bn4 < N;

    const int m = bm + am;
    const int bb = m >> 10, l = m & 1023;
    const float4* cw4 = reinterpret_cast<const float4*>(cw);

    uint32_t sAs = (uint32_t)__cvta_generic_to_shared(&sm.As[0][0]);
    uint32_t sBs = (uint32_t)__cvta_generic_to_shared(&sm.Bs[0][0]);

    float4 aR;
    auto ldA = [&](int it) {
        int k = kstart + it * BK + akq;
        float4 a = *reinterpret_cast<const float4*>(cb + k);
        float* ap = &a.x;
        float4 w0 = cw4[k], w1 = cw4[k + 1], w2 = cw4[k + 2], w3 = cw4[k + 3];
        const float* wf0 = &w0.x; const float* wf1 = &w1.x;
        const float* wf2 = &w2.x; const float* wf3 = &w3.x;
        #pragma unroll
        for (int jj = 0; jj < 4; jj++) {
            int ll = l - 3 + jj;
            if (ll >= 0) {
                float4 xv = *reinterpret_cast<const float4*>(
                    xz + ((size_t)(bb << 10) + ll) * (2 * D) + k);
                ap[0] = fmaf(xv.x, wf0[jj], ap[0]);
                ap[1] = fmaf(xv.y, wf1[jj], ap[1]);
                ap[2] = fmaf(xv.z, wf2[jj], ap[2]);
                ap[3] = fmaf(xv.w, wf3[jj], ap[3]);
            }
        }
        #pragma unroll
        for (int i = 0; i < 4; i++) ap[i] = ap[i] / (1.f + __expf(-ap[i]));
        aR = a;
    };
    auto stA = [&](int buf) {
        *reinterpret_cast<float4*>(&sm.As[buf][am * ASTRIDE + akq]) = aR;
    };
    auto cpB = [&](int it, int buf) {
        int k = kstart + it * BK + bkb;
        const float* src = bn_ok ? (Bm + (size_t)k * N + bn4) : Bm;
        cp_async16(sBs + (buf * BK * BN + bkb * BN + bn4) * 4, src, bn_ok);
        cp_commit();
    };

    const int ty = tid >> 4, tx = tid & 15;
    const int m0 = ty * 4, n0 = tx * 4;

    ull acc2[4][2];
    #pragma unroll
    for (int i = 0; i < 4; i++) { acc2[i][0] = 0ull; acc2[i][1] = 0ull; }

    ldA(0); stA(0); cpB(0, 0);
    for (int it = 0; it < niters; it++) {
        cp_wait<0>();
        __syncthreads();
        const int buf = it & 1;
        if (it + 1 < niters) ldA(it + 1);     // LDGs overlap compute
        gemm_inner(&sm.As[buf][0], &sm.Bs[buf][0], m0, n0, acc2);
        __syncthreads();
        if (it + 1 < niters) { stA(buf ^ 1); cpB(it + 1, buf ^ 1); }
    }

    #pragma unroll
    for (int i = 0; i < 4; i++) {
        int row = bm + m0 + i;
        float v[4];
        unpack2(acc2[i][0], v[0], v[1]);
        unpack2(acc2[i][1], v[2], v[3]);
        #pragma unroll
        for (int j = 0; j < 4; j++) {
            int col = n0 + j;
            if (col < N) atomicAdd(&C[(size_t)row * N + col], v[j]);
        }
    }
}

// ------------------------- patchify GEMM (im2col fused, split-K) -----------
__global__ void sgemm_patch_k(const float* __restrict__ X,
                              const float* __restrict__ Bm,
                              float* __restrict__ C)
{
    __shared__ SmemGemm sm;
    const int bm = blockIdx.y * BM, bn = blockIdx.x * BN;
    const int tid = threadIdx.x;
    const int N = D;

    const int kc = PATCH_DIM / gridDim.z;
    const int kstart = blockIdx.z * kc;
    const int niters = kc / BK;

    const int am  = tid >> 2;
    const int akq = (tid & 3) << 2;
    const int bkb = tid >> 4;
    const int bn4 = (tid & 15) << 2;

    const int m = bm + am;
    const int b = m >> 10, l = m & 1023;
    const int gh = l >> 6, gw = (l >> 3) & 7, gd = l & 7;
    const size_t xbase = ((size_t)(b * 256 + gh * 16) * 256 + gw * 32) * 64 + gd * 8;

    uint32_t sAs = (uint32_t)__cvta_generic_to_shared(&sm.As[0][0]);
    uint32_t sBs = (uint32_t)__cvta_generic_to_shared(&sm.Bs[0][0]);

    auto load_stage = [&](int it, int buf) {
        int k0 = kstart + it * BK;
        {
            int k = k0 + akq;
            int ph = k >> 8, pw = (k >> 3) & 31, pd = k & 7;
            const float* src = X + xbase + (size_t)ph * 16384 + pw * 64 + pd;
            cp_async16(sAs + (buf * BM * ASTRIDE + am * ASTRIDE + akq) * 4, src, true);
        }
        {
            int k = k0 + bkb;
            const float* src = Bm + (size_t)k * N + bn + bn4;
            cp_async16(sBs + (buf * BK * BN + bkb * BN + bn4) * 4, src, true);
        }
    };

    const int ty = tid >> 4, tx = tid & 15;
    const int m0 = ty * 4, n0 = tx * 4;

    ull acc2[4][2];
    #pragma unroll
    for (int i = 0; i < 4; i++) { acc2[i][0] = 0ull; acc2[i][1] = 0ull; }

    load_stage(0, 0); cp_commit();
    load_stage(1, 1); cp_commit();

    for (int it = 0; it < niters; it++) {
        cp_wait<1>();
        __syncthreads();
        const int buf = it & 1;
        gemm_inner(&sm.As[buf][0], &sm.Bs[buf][0], m0, n0, acc2);
        __syncthreads();
        if (it + 2 < niters) load_stage(it + 2, buf);
        cp_commit();
    }

    #pragma unroll
    for (int i = 0; i < 4; i++) {
        int row = bm + m0 + i;
        float v[4];
        unpack2(acc2[i][0], v[0], v[1]);
        unpack2(acc2[i][1], v[2], v[3]);
        #pragma unroll
        for (int j = 0; j < 4; j++)
            atomicAdd(&C[(size_t)row * N + bn + n0 + j], v[j]);
    }
}

// ------------------------- zero buffer --------------------------------------
__global__ void zero_k(float* __restrict__ p, int n) {
    int i = blockIdx.x * blockDim.x + threadIdx.x;
    if (i < n) p[i] = 0.f;
}

// ------------------------- LayerNorm + xz/dbl/flag zeroing -----------------
__global__ void ln_k(const float* __restrict__ in, float* __restrict__ out,
                     const float* __restrict__ w, const float* __restrict__ b,
                     float* __restrict__ zdbl, float* __restrict__ zxz,
                     int* __restrict__ zflag)
{
    int row = blockIdx.x;
    int t = threadIdx.x;   // 128 threads
    if (zdbl != nullptr && t < DBL_N) zdbl[(size_t)row * DBL_N + t] = 0.f;
    if (zxz != nullptr) {
        float* zr = zxz + (size_t)row * (2 * D);
        #pragma unroll
        for (int q = 0; q < 6; q++) zr[t + q * 128] = 0.f;
    }
    if (zflag != nullptr && row < 6) zflag[row * 128 + t] = 0;
    const float* r = in + (size_t)row * D;
    float v0 = r[t], v1 = r[t + 128], v2 = r[t + 256];
    float s = v0 + v1 + v2;
    __shared__ float sh[4], sh2[4];
    #pragma unroll
    for (int o = 16; o; o >>= 1) s += __shfl_xor_sync(~0u, s, o);
    if ((t & 31) == 0) sh[t >> 5] = s;
    __syncthreads();
    float mu = (sh[0] + sh[1] + sh[2] + sh[3]) * (1.f / 384.f);
    float d0 = v0 - mu, d1 = v1 - mu, d2 = v2 - mu;
    float q = d0 * d0 + d1 * d1 + d2 * d2;
    #pragma unroll
    for (int o = 16; o; o >>= 1) q += __shfl_xor_sync(~0u, q, o);
    if ((t & 31) == 0) sh2[t >> 5] = q;
    __syncthreads();
    float var = (sh2[0] + sh2[1] + sh2[2] + sh2[3]) * (1.f / 384.f);
    float rs = rsqrtf(var + 1e-5f);
    float* o = out + (size_t)row * D;
    o[t]       = d0 * rs * w[t]       + b[t];
    o[t + 128] = d1 * rs * w[t + 128] + b[t + 128];
    o[t + 256] = d2 * rs * w[t + 256] + b[t + 256];
}

// ------------------------- positional embedding + patch bias ---------------
__global__ void posembed_k(const float* __restrict__ bp,
                           const unsigned char* __restrict__ mask,
                           const float* __restrict__ patch_b)
{
    int row = blockIdx.x;           // NTOK
    int d = threadIdx.x;            // 384
    int b = row >> 10, l = row & 1023;
    int gh = l >> 6, gw = (l >> 3) & 7, gd = l & 7;
    float vr = bp[b * 4 + 2];
    bool m = mask[b] != 0;
    int j = d / 128, r = d - j * 128, f = r & 63;
    float c;
    if (j == 0)      c = (float)gh * (1.f / 15.f);
    else if (j == 1) c = ((float)gw - 4.f) * 0.25f;
    else {
        float v = m ? ((float)gd - 4.f) * vr : (float)gd * vr;
        float den = m ? 4.f * vr : 7.f * vr;
        c = v / den;
    }
    float omega = powf(10000.f, -(float)f * (1.f / 64.f));
    float ph = c * omega;
    float pe = (r < 64) ? sinf(ph) : cosf(ph);
    g_tok[(size_t)row * D + d] += pe + patch_b[d];
}

// ------------------------- single-pass chunked scan (conv+dt inline) -------
struct ScanTile {
    __align__(16) float dtr[CHL][DTRANK];  // 12 KB; reused as zz|yy later
    __align__(16) float xz_s[132][SCH];    // 4.2 KB xz slice rows l0-3..l0+127
    __align__(16) float bc[CHL][32];       // 16 KB  B[16] | C[16]
    __align__(16) float dt[CHL][SCH];      //  4 KB
    __align__(16) float xc[CHL][SCH];      //  4 KB
    __align__(16) float dtw[DTRANK][SCH];  // 768 B
    __align__(16) float cw_s[SCH][4];      // 128 B
    float dtb[SCH];
    float cb_s[SCH];
};

__global__ void scan_k(const float* __restrict__ A_log,
                       const float* __restrict__ dtw,
                       const float* __restrict__ dtb,
                       const float* __restrict__ cw,
                       const float* __restrict__ cb,
                       const float* __restrict__ Dsk)
{
    __shared__ ScanTile sm;
    const int tid = threadIdx.x;
    const int grp = tid >> 4, lane = tid & 15;
    const int c = blockIdx.y;
    const int blk = blockIdx.x;             // 0..95
    const int b = blk / 48;
    const int d0 = (blk % 48) * SCH;
    const int d = d0 + grp;
    const int l0 = c * CHL;

    const float* dbl_b = g_dbl + (size_t)b * L * DBL_N;
    const float* xz_b  = g_xz + (size_t)b * L * (2 * D);

    uint32_t s_dtr = (uint32_t)__cvta_generic_to_shared(&sm.dtr[0][0]);
    uint32_t s_xzs = (uint32_t)__cvta_generic_to_shared(&sm.xz_s[0][0]);
    uint32_t s_bc  = (uint32_t)__cvta_generic_to_shared(&sm.bc[0][0]);
    uint32_t s_dtw = (uint32_t)__cvta_generic_to_shared(&sm.dtw[0][0]);
    uint32_t s_cw  = (uint32_t)__cvta_generic_to_shared(&sm.cw_s[0][0]);

    // stage dtr (dbl[:, :24])
    #pragma unroll
    for (int q = 0; q < 6; q++) {
        int qq = tid + q * 128;
        int row = qq / 6, part = (qq % 6) << 2;
        cp_async16(s_dtr + (row * DTRANK + part) * 4,
                   dbl_b + (size_t)(l0 + row) * DBL_N + part, true);
    }
    // stage xz slice rows l0-3 .. l0+127 (zfill l < 0)
    #pragma unroll
    for (int q = 0; q < 3; q++) {
        int qq = tid + q * 128;
        if (qq < 262) {
            int row = qq >> 1, part = (qq & 1) << 2;
            int l = l0 - 3 + row;
            const float* src = (l >= 0) ? (xz_b + (size_t)l * (2 * D) + d0 + part) : xz_b;
            cp_async16(s_xzs + (row * SCH + part) * 4, src, l >= 0);
        }
    }
    // stage bc (dbl[:, 24:56])
    #pragma unroll
    for (int q = 0; q < 8; q++) {
        int qq = tid + q * 128;
        int row = qq >> 3, part = (qq & 7) << 2;
        cp_async16(s_bc + (row * 32 + part) * 4,
                   dbl_b + (size_t)(l0 + row) * DBL_N + DTRANK + part, true);
    }
    // dtw / cw / scalars
    if (tid < 48) {
        int r = tid >> 1, part = (tid & 1) << 2;
        cp_async16(s_dtw + (r * SCH + part) * 4,
                   dtw + (size_t)r * D + d0 + part, true);
    }
    if (tid < SCH) {
        cp_async16(s_cw + tid * 16, cw + (size_t)(d0 + tid) * 4, true);
        sm.dtb[tid]  = __ldg(&dtb[d0 + tid]);
        sm.cb_s[tid] = __ldg(&cb[d0 + tid]);
    }
    cp_commit();

    const float Aa = -__expf(A_log[d * DSTATE + lane]);
    const float Dp = __ldg(&Dsk[d]);

    cp_wait<0>();
    __syncthreads();

    // inline dt_proj (thread = row tid)
    {
        float acc[SCH];
        #pragma unroll
        for (int j = 0; j < SCH; j++) acc[j] = sm.dtb[j];
        #pragma unroll
        for (int r = 0; r < DTRANK; r += 4) {
            float4 v = *reinterpret_cast<const float4*>(&sm.dtr[tid][r]);
            const float* vf = &v.x;
            #pragma unroll
            for (int cc = 0; cc < 4; cc++)
                #pragma unroll
                for (int j = 0; j < SCH; j++)
                    acc[j] = fmaf(vf[cc], sm.dtw[r + cc][j], acc[j]);
        }
        #pragma unroll
        for (int j = 0; j < SCH; j++)
            sm.dt[tid][j] = (acc[j] > 20.f) ? acc[j] : log1pf(__expf(acc[j]));
    }
    // inline conv + silu -> xc (thread = row tid; window rows tid..tid+3)
    {
        float accx[SCH];
        #pragma unroll
        for (int j = 0; j < SCH; j++) accx[j] = sm.cb_s[j];
        #pragma unroll
        for (int jj = 0; jj < 4; jj++) {
            float4 v0 = *reinterpret_cast<const float4*>(&sm.xz_s[tid + jj][0]);
            float4 v1 = *reinterpret_cast<const float4*>(&sm.xz_s[tid + jj][4]);
            accx[0] = fmaf(v0.x, sm.cw_s[0][jj], accx[0]);
            accx[1] = fmaf(v0.y, sm.cw_s[1][jj], accx[1]);
            accx[2] = fmaf(v0.z, sm.cw_s[2][jj], accx[2]);
            accx[3] = fmaf(v0.w, sm.cw_s[3][jj], accx[3]);
            accx[4] = fmaf(v1.x, sm.cw_s[4][jj], accx[4]);
            accx[5] = fmaf(v1.y, sm.cw_s[5][jj], accx[5]);
            accx[6] = fmaf(v1.z, sm.cw_s[6][jj], accx[6]);
            accx[7] = fmaf(v1.w, sm.cw_s[7][jj], accx[7]);
        }
        #pragma unroll
        for (int j = 0; j < SCH; j++)
            sm.xc[tid][j] = accx[j] / (1.f + __expf(-accx[j]));
    }
    __syncthreads();   // dtr reads complete -> region reusable

    // stage zz into the dead dtr region (overlaps local scan + chain)
    float* zzp = &sm.dtr[0][0];                 // [CHL][SCH]
    float* yyp = zzp + CHL * SCH;               // [CHL][SCH]
    {
        uint32_t s_zz = (uint32_t)__cvta_generic_to_shared(zzp);
        const float* z_g = xz_b + D;
        #pragma unroll
        for (int q = 0; q < 2; q++) {
            int qq = tid + q * 128;
            int row = qq >> 1, part = (qq & 1) << 2;
            cp_async16(s_zz + (row * SCH + part) * 4,
                       z_g + (size_t)(l0 + row) * (2 * D) + d0 + part, true);
        }
        cp_commit();
    }

    // local scan with h0 = 0 -> (P, W)
    float h = 0.f, P = 1.f;
    #pragma unroll 8
    for (int l = 0; l < CHL; l++) {
        float dtv = sm.dt[l][grp];
        float uv  = sm.xc[l][grp];
        float Bv  = sm.bc[l][lane];
        float dA  = __expf(dtv * Aa);
        h = fmaf(h, dA, dtv * uv * Bv);
        P *= dA;
    }

    // chained prefix: wait predecessor chunk, fold, publish inclusive state
    float hprev = 0.f;
    if (c > 0) {
        if (tid == 0) {
            volatile int* f = &g_flag[(c - 1) * 96 + blk];
            while (*f == 0) { }
        }
        __syncthreads();
        volatile float* hp = &g_H[((size_t)blk * NCH + (c - 1)) * 128 + tid];
        hprev = *hp;
    }
    float Hc = fmaf(hprev, P, h);
    g_H[((size_t)blk * NCH + c) * 128 + tid] = Hc;
    __threadfence();
    __syncthreads();
    if (tid == 0) atomicExch(&g_flag[c * 96 + blk], 1);

    // replay with true h0 = hprev
    cp_wait<0>();
    __syncthreads();
    h = hprev;
    #pragma unroll 8
    for (int l = 0; l < CHL; l++) {
        float dtv = sm.dt[l][grp];
        float uv  = sm.xc[l][grp];
        float Bv  = sm.bc[l][lane];
        float Cv  = sm.bc[l][lane + 16];
        float dA  = __expf(dtv * Aa);
        h = fmaf(h, dA, dtv * uv * Bv);
        float p = h * Cv;
        p += __shfl_xor_sync(0xffffffffu, p, 8);
        p += __shfl_xor_sync(0xffffffffu, p, 4);
        p += __shfl_xor_sync(0xffffffffu, p, 2);
        p += __shfl_xor_sync(0xffffffffu, p, 1);
        if (lane == 0) {
            float zv = zzp[l * SCH + grp];
            float sz = zv / (1.f + __expf(-zv));
            yyp[l * SCH + grp] = (p + uv * Dp) * sz;
        }
    }
    __syncthreads();

    float* y_g = g_y + (size_t)(b * L + l0 + tid) * D + d0;
    float4 v0 = *reinterpret_cast<const float4*>(&yyp[tid * SCH]);
    float4 v1 = *reinterpret_cast<const float4*>(&yyp[tid * SCH + 4]);
    *reinterpret_cast<float4*>(y_g)     = v0;
    *reinterpret_cast<float4*>(y_g + 4) = v1;
}

// ------------------------- launch ------------------------------------------
extern "C" void kernel_launch(void* const* d_in, const int* in_sizes, int n_in,
                              void* d_out, int out_size)
{
    const float* x          = (const float*)d_in[0];
    const float* bp         = (const float*)d_in[1];
    const float* patch_w    = (const float*)d_in[2];
    const float* patch_b    = (const float*)d_in[3];
    const float* in_proj_w  = (const float*)d_in[4];
    const float* conv_w     = (const float*)d_in[5];
    const float* conv_b     = (const float*)d_in[6];
    const float* x_proj_w   = (const float*)d_in[7];
    const float* dt_proj_w  = (const float*)d_in[8];
    const float* dt_proj_b  = (const float*)d_in[9];
    const float* A_log      = (const float*)d_in[10];
    const float* Dskip      = (const float*)d_in[11];
    const float* out_proj_w = (const float*)d_in[12];
    const float* norm_w     = (const float*)d_in[13];
    const float* norm_b     = (const float*)d_in[14];
    const float* fw         = (const float*)d_in[15];
    const float* fb         = (const float*)d_in[16];
    const unsigned char* mask = (const unsigned char*)d_in[17];

    float *tok, *h, *xz, *dbl, *y;
    int* flg;
    cudaGetSymbolAddress((void**)&tok, g_tok);
    cudaGetSymbolAddress((void**)&h,   g_h);
    cudaGetSymbolAddress((void**)&xz,  g_xz);
    cudaGetSymbolAddress((void**)&dbl, g_dbl);
    cudaGetSymbolAddress((void**)&y,   g_y);
    cudaGetSymbolAddress((void**)&flg, g_flag);

    // patchify: zero tok, split-K=4 accumulate, bias+posembed fused
    zero_k<<<(NTOK * D + 255) / 256, 256>>>(tok, NTOK * D);
    sgemm_patch_k<<<dim3(D / 64, NTOK / 64, 4), 256>>>(x, patch_w, tok);
    posembed_k<<<NTOK, D>>>(bp, mask, patch_b);

    for (int layer = 0; layer < DEPTH; layer++) {
        ln_k<<<NTOK, 128>>>(tok, h, norm_w + layer * D, norm_b + layer * D,
                            dbl, xz, flg);
        sgemm_k<<<dim3((2 * D) / 64, NTOK / 64, 3), 256>>>(h, D,
                in_proj_w + (size_t)layer * D * 2 * D, xz, nullptr, NTOK, 2 * D, D, 0);
        sgemm_xproj_k<<<dim3(1, NTOK / 64, 6), 256>>>(xz,
                conv_w + (size_t)layer * D * 4, conv_b + (size_t)layer * D,
                x_proj_w + (size_t)layer * D * DBL_N, dbl);
        scan_k<<<dim3(96, NCH), 128>>>(A_log + (size_t)layer * D * DSTATE,
                                       dt_proj_w + (size_t)layer * DTRANK * D,
                                       dt_proj_b + (size_t)layer * D,
                                       conv_w + (size_t)layer * D * 4,
                                       conv_b + (size_t)layer * D,
                                       Dskip + (size_t)layer * D);
        sgemm_k<<<dim3(D / 64, NTOK / 64, 3), 256>>>(y, D,
                out_proj_w + (size_t)layer * D * D, tok, nullptr, NTOK, D, D, 3);
    }

    ln_k<<<NTOK, 128>>>(tok, (float*)d_out, fw, fb, nullptr, nullptr, nullptr);
}